// round 1
// baseline (speedup 1.0000x reference)
#include <cuda_runtime.h>
#include <cstdint>

// Problem constants (fixed shapes: B=8, C=14, H=512, W=512)
#define DELTA_   0.7f
#define FUS_WI_  0.01f
#define Cc       14
#define HW       262144      // 512*512
#define LOG2HW   18
#define BHW      2097152     // 8*HW
#define CHW      (Cc*HW)
#define NG       (BHW/4)     // pixel groups of 4
#define TPB      256
#define NBLK     (NG/TPB)    // 2048

__device__ int          g_min;
__device__ unsigned int g_cm[Cc*Cc];
__device__ float        g_wc[Cc*Cc];
__device__ float        g_part_ce[NBLK];
__device__ float        g_part_loss[NBLK];

// ---- packed f32x2 helpers (sm_100+) ----
__device__ __forceinline__ unsigned long long pack2(float lo, float hi){
    unsigned long long r;
    asm("mov.b64 %0, {%1, %2};" : "=l"(r) : "f"(lo), "f"(hi));
    return r;
}
__device__ __forceinline__ void unpack2(unsigned long long v, float& lo, float& hi){
    asm("mov.b64 {%0, %1}, %2;" : "=f"(lo), "=f"(hi) : "l"(v));
}
__device__ __forceinline__ unsigned long long fma2(unsigned long long a, unsigned long long b, unsigned long long c){
    unsigned long long d;
    asm("fma.rn.f32x2 %0, %1, %2, %3;" : "=l"(d) : "l"(a), "l"(b), "l"(c));
    return d;
}
__device__ __forceinline__ unsigned long long mul2(unsigned long long a, unsigned long long b){
    unsigned long long d;
    asm("mul.rn.f32x2 %0, %1, %2;" : "=l"(d) : "l"(a), "l"(b));
    return d;
}

__device__ __forceinline__ float blockReduce(float v, float* red){
    int t = threadIdx.x;
    red[t] = v; __syncthreads();
    #pragma unroll
    for(int s = TPB/2; s > 0; s >>= 1){
        if(t < s) red[t] += red[t+s];
        __syncthreads();
    }
    return red[0];
}

// ---------------- init ----------------
__global__ void k_init(){
    int t = threadIdx.x;
    if(t < Cc*Cc) g_cm[t] = 0u;
    if(t == 0)    g_min = 0x7fffffff;
}

// ---------------- min of y_true ----------------
__global__ void k_min(const int* __restrict__ yt){
    __shared__ int red[TPB];
    int tid = blockIdx.x*blockDim.x + threadIdx.x;
    int stride = gridDim.x*blockDim.x;
    int mn = 0x7fffffff;
    const int4* y4 = (const int4*)yt;
    for(int i = tid; i < BHW/4; i += stride){
        int4 v = y4[i];
        mn = min(mn, min(min(v.x, v.y), min(v.z, v.w)));
    }
    red[threadIdx.x] = mn; __syncthreads();
    #pragma unroll
    for(int s = TPB/2; s > 0; s >>= 1){
        if(threadIdx.x < s) red[threadIdx.x] = min(red[threadIdx.x], red[threadIdx.x+s]);
        __syncthreads();
    }
    if(threadIdx.x == 0) atomicMin(&g_min, red[0]);
}

// ---------------- pass 1: ce sum + confusion matrix ----------------
__global__ void __launch_bounds__(TPB) k_pass1(
    const float* __restrict__ yp, const float* __restrict__ weight,
    const int* __restrict__ ytg, const int* __restrict__ blg)
{
    __shared__ unsigned int scm[Cc*Cc];
    __shared__ float swt[Cc];
    __shared__ float red[TPB];
    int t = threadIdx.x;
    if(t < Cc*Cc) scm[t] = 0u;
    if(t < Cc)    swt[t] = weight[t];
    __syncthreads();

    int gid = blockIdx.x*TPB + t;
    int p0  = gid*4;
    int b   = p0 >> LOG2HW;
    int hw  = p0 & (HW-1);
    const float4* base = (const float4*)(yp + (size_t)b*CHW + hw);

    float4 v[Cc];
    #pragma unroll
    for(int c = 0; c < Cc; c++) v[c] = base[c*(HW/4)];

    int4 yt4 = ((const int4*)ytg)[gid];
    int4 bl4 = ((const int4*)blg)[gid];
    int mn = g_min;
    int y0 = (yt4.x==255)?mn:yt4.x;
    int y1 = (yt4.y==255)?mn:yt4.y;
    int y2 = (yt4.z==255)?mn:yt4.z;
    int y3 = (yt4.w==255)?mn:yt4.w;

    float4 mx = v[0];
    int amx=0, amy=0, amz=0, amw=0;
    float4 xt;
    xt.x = (y0==0)? v[0].x : 0.0f;
    xt.y = (y1==0)? v[0].y : 0.0f;
    xt.z = (y2==0)? v[0].z : 0.0f;
    xt.w = (y3==0)? v[0].w : 0.0f;
    #pragma unroll
    for(int c = 1; c < Cc; c++){
        if(v[c].x > mx.x){ mx.x = v[c].x; amx = c; }
        if(v[c].y > mx.y){ mx.y = v[c].y; amy = c; }
        if(v[c].z > mx.z){ mx.z = v[c].z; amz = c; }
        if(v[c].w > mx.w){ mx.w = v[c].w; amw = c; }
        if(c == y0) xt.x = v[c].x;
        if(c == y1) xt.y = v[c].y;
        if(c == y2) xt.z = v[c].z;
        if(c == y3) xt.w = v[c].w;
    }
    float4 se = {0.f,0.f,0.f,0.f};
    #pragma unroll
    for(int c = 0; c < Cc; c++){
        se.x += __expf(v[c].x - mx.x);
        se.y += __expf(v[c].y - mx.y);
        se.z += __expf(v[c].z - mx.z);
        se.w += __expf(v[c].w - mx.w);
    }
    float bl0 = (float)bl4.x + ((bl4.x==0)?0.4f:0.0f);
    float bl1 = (float)bl4.y + ((bl4.y==0)?0.4f:0.0f);
    float bl2 = (float)bl4.z + ((bl4.z==0)?0.4f:0.0f);
    float bl3 = (float)bl4.w + ((bl4.w==0)?0.4f:0.0f);

    float ce =
        swt[y0]*(mx.x + __logf(se.x) - xt.x)*bl0 +
        swt[y1]*(mx.y + __logf(se.y) - xt.y)*bl1 +
        swt[y2]*(mx.z + __logf(se.z) - xt.z)*bl2 +
        swt[y3]*(mx.w + __logf(se.w) - xt.w)*bl3;

    atomicAdd(&scm[y0*Cc + amx], 1u);
    atomicAdd(&scm[y1*Cc + amy], 1u);
    atomicAdd(&scm[y2*Cc + amz], 1u);
    atomicAdd(&scm[y3*Cc + amw], 1u);

    float tot = blockReduce(ce, red);
    if(t == 0) g_part_ce[blockIdx.x] = tot;
    // blockReduce ends with __syncthreads -> scm atomics are complete
    if(t < Cc*Cc) atomicAdd(&g_cm[t], scm[t]);
}

// ---------------- wc from confusion matrix ----------------
__global__ void k_wc(const float* __restrict__ wei_confus){
    __shared__ float cs[Cc*Cc];
    __shared__ float col[Cc];
    int t = threadIdx.x;
    if(t < Cc*Cc) cs[t] = (float)g_cm[t];
    __syncthreads();
    if(t < Cc){
        float s = 0.f;
        #pragma unroll
        for(int r = 0; r < Cc; r++) s += cs[r*Cc + t];
        col[t] = (s == 0.0f) ? 1.0f : s;
    }
    __syncthreads();
    if(t < Cc*Cc){
        int k = t % Cc;
        float bat = cs[t] / col[k];
        g_wc[t] = (wei_confus[t] + bat*FUS_WI_) / (1.0f + FUS_WI_);
    }
}

// ---------------- pass 2: proj + relu losses (reversed order for L2 reuse) ----------------
__global__ void __launch_bounds__(TPB) k_pass2(
    const float* __restrict__ yp,
    const int* __restrict__ ytg, const int* __restrict__ blg)
{
    __shared__ unsigned long long swc2[Cc*Cc];
    __shared__ float red[TPB];
    int t = threadIdx.x;
    for(int i = t; i < Cc*Cc; i += TPB){
        float w = g_wc[i];
        swc2[i] = pack2(w, w);
    }
    __syncthreads();

    int gid = blockIdx.x*TPB + t;
    int g   = (NG-1) - gid;          // reverse order: re-hit pass-1's L2 tail first
    int p0  = g*4;
    int b   = p0 >> LOG2HW;
    int hw  = p0 & (HW-1);
    const float4* base = (const float4*)(yp + (size_t)b*CHW + hw);

    float4 v[Cc];
    #pragma unroll
    for(int c = 0; c < Cc; c++) v[c] = base[c*(HW/4)];

    int4 yt4 = ((const int4*)ytg)[g];
    int4 bl4 = ((const int4*)blg)[g];
    int mn = g_min;
    int y0 = (yt4.x==255)?mn:yt4.x;
    int y1 = (yt4.y==255)?mn:yt4.y;
    int y2 = (yt4.z==255)?mn:yt4.z;
    int y3 = (yt4.w==255)?mn:yt4.w;

    float4 mx = v[0];
    #pragma unroll
    for(int c = 1; c < Cc; c++){
        mx.x = fmaxf(mx.x, v[c].x); mx.y = fmaxf(mx.y, v[c].y);
        mx.z = fmaxf(mx.z, v[c].z); mx.w = fmaxf(mx.w, v[c].w);
    }
    unsigned long long e01[Cc], e23[Cc];
    float4 se = {0.f,0.f,0.f,0.f};
    #pragma unroll
    for(int c = 0; c < Cc; c++){
        float ex = __expf(v[c].x - mx.x), ey = __expf(v[c].y - mx.y);
        float ez = __expf(v[c].z - mx.z), ew = __expf(v[c].w - mx.w);
        se.x += ex; se.y += ey; se.z += ez; se.w += ew;
        e01[c] = pack2(ex, ey);
        e23[c] = pack2(ez, ew);
    }
    unsigned long long inv01 = pack2(__fdividef(1.0f, se.x), __fdividef(1.0f, se.y));
    unsigned long long inv23 = pack2(__fdividef(1.0f, se.z), __fdividef(1.0f, se.w));
    #pragma unroll
    for(int c = 0; c < Cc; c++){
        e01[c] = mul2(e01[c], inv01);
        e23[c] = mul2(e23[c], inv23);
    }

    float l0 = 0.f, l1 = 0.f, l2 = 0.f, l3 = 0.f;
    #pragma unroll
    for(int k = 0; k < Cc; k++){
        unsigned long long a01 = 0ull, a23 = 0ull;   // (0.0f, 0.0f)
        #pragma unroll
        for(int c = 0; c < Cc; c++){
            unsigned long long w2 = swc2[c*Cc + k];
            a01 = fma2(e01[c], w2, a01);
            a23 = fma2(e23[c], w2, a23);
        }
        float pa, pb, pc, pd;
        unpack2(a01, pa, pb);
        unpack2(a23, pc, pd);
        l0 += fmaxf(((k==y0)?1.0f:0.0f) - pa, 0.0f);
        l1 += fmaxf(((k==y1)?1.0f:0.0f) - pb, 0.0f);
        l2 += fmaxf(((k==y2)?1.0f:0.0f) - pc, 0.0f);
        l3 += fmaxf(((k==y3)?1.0f:0.0f) - pd, 0.0f);
    }
    float bl0 = (float)bl4.x + ((bl4.x==0)?0.4f:0.0f);
    float bl1 = (float)bl4.y + ((bl4.y==0)?0.4f:0.0f);
    float bl2 = (float)bl4.z + ((bl4.z==0)?0.4f:0.0f);
    float bl3 = (float)bl4.w + ((bl4.w==0)?0.4f:0.0f);

    float acc = (l0*bl0 + l1*bl1 + l2*bl2 + l3*bl3) * (1.0f/(float)Cc);
    float tot = blockReduce(acc, red);
    if(t == 0) g_part_loss[blockIdx.x] = tot;
}

// ---------------- final scalar ----------------
__global__ void k_final(float* __restrict__ out){
    __shared__ float red[TPB];
    int t = threadIdx.x;
    float s = 0.f;
    for(int i = t; i < NBLK; i += TPB)
        s += g_part_loss[i] + DELTA_*g_part_ce[i];
    float tot = blockReduce(s, red);
    if(t == 0) out[0] = tot / (float)BHW;
}

extern "C" void kernel_launch(void* const* d_in, const int* in_sizes, int n_in,
                              void* d_out, int out_size) {
    const float* y_pred     = (const float*)d_in[0];
    const float* wei_confus = (const float*)d_in[1];
    const float* weight     = (const float*)d_in[2];
    const int*   y_true     = (const int*)d_in[3];
    const int*   backlabel  = (const int*)d_in[4];
    float* out = (float*)d_out;

    k_init <<<1, 256>>>();
    k_min  <<<64, TPB>>>(y_true);
    k_pass1<<<NBLK, TPB>>>(y_pred, weight, y_true, backlabel);
    k_wc   <<<1, 256>>>(wei_confus);
    k_pass2<<<NBLK, TPB>>>(y_pred, y_true, backlabel);
    k_final<<<1, TPB>>>(out);
}